// round 9
// baseline (speedup 1.0000x reference)
#include <cuda_runtime.h>

#define BB  64
#define TT  4096
#define HH  1024
#define NHH 4

// Scratch: h = x @ W^T + b : [B, T, NH] = 4 MB (L2-resident for the scan)
__device__ float g_h[BB * TT * NHH];

// ---------------------------------------------------------------------------
// Kernel 1: tall-skinny GEMV. One warp computes 4 consecutive (b,t) rows.
// __launch_bounds__(256,4) caps regs at 64 -> 4 blocks/SM (vs 3 at 75 regs).
// ---------------------------------------------------------------------------
__global__ __launch_bounds__(256, 4) void k_gemv(const float* __restrict__ x,
                                                 const float* __restrict__ W,
                                                 const float* __restrict__ bias) {
    __shared__ float4 sW[NHH * (HH / 4)];  // 16 KB
    for (int i = threadIdx.x; i < NHH * (HH / 4); i += 256)
        sW[i] = reinterpret_cast<const float4*>(W)[i];
    __syncthreads();

    const int ROWS = 4;
    int warp_global = (blockIdx.x * 256 + threadIdx.x) >> 5;
    int lane = threadIdx.x & 31;
    long row0 = (long)warp_global * ROWS;

    float acc[ROWS][NHH];
#pragma unroll
    for (int r = 0; r < ROWS; r++)
#pragma unroll
        for (int n = 0; n < NHH; n++) acc[r][n] = 0.0f;

    const float4* xp = reinterpret_cast<const float4*>(x) + row0 * (HH / 4);

#pragma unroll
    for (int k = 0; k < (HH / 4) / 32; k++) {  // 8 iterations
        int idx = lane + k * 32;
        float4 w0 = sW[0 * (HH / 4) + idx];
        float4 w1 = sW[1 * (HH / 4) + idx];
        float4 w2 = sW[2 * (HH / 4) + idx];
        float4 w3 = sW[3 * (HH / 4) + idx];
#pragma unroll
        for (int r = 0; r < ROWS; r++) {
            float4 xv = xp[(long)r * (HH / 4) + idx];
            acc[r][0] += xv.x * w0.x + xv.y * w0.y + xv.z * w0.z + xv.w * w0.w;
            acc[r][1] += xv.x * w1.x + xv.y * w1.y + xv.z * w1.z + xv.w * w1.w;
            acc[r][2] += xv.x * w2.x + xv.y * w2.y + xv.z * w2.z + xv.w * w2.w;
            acc[r][3] += xv.x * w3.x + xv.y * w3.y + xv.z * w3.z + xv.w * w3.w;
        }
    }

#pragma unroll
    for (int r = 0; r < ROWS; r++)
#pragma unroll
        for (int n = 0; n < NHH; n++)
#pragma unroll
            for (int off = 16; off > 0; off >>= 1)
                acc[r][n] += __shfl_xor_sync(0xffffffffu, acc[r][n], off);

    if (lane == 0) {
        float b0 = bias[0], b1 = bias[1], b2 = bias[2], b3 = bias[3];
#pragma unroll
        for (int r = 0; r < ROWS; r++) {
            float4 o = make_float4(acc[r][0] + b0, acc[r][1] + b1,
                                   acc[r][2] + b2, acc[r][3] + b3);
            reinterpret_cast<float4*>(g_h)[row0 + r] = o;
        }
    }
}

// ---------------------------------------------------------------------------
// Kernel 2: fused chunked EMA scan + running max + head projection.
// 64 blocks (one per batch) x 1024 threads (4 heads x 256 threads).
// Each thread owns a 16-step chunk; two-level affine-map scan per head;
// final out[b] computed in-block (no k_final, no g_part round-trip).
// ---------------------------------------------------------------------------
__global__ __launch_bounds__(1024) void k_scan(const float* __restrict__ decay,
                                               const float* __restrict__ head_w,
                                               float* __restrict__ out) {
    const int CH = TT / 256;  // 16
    int b = blockIdx.x;
    int n = threadIdx.x >> 8;          // head 0..3
    int tid = threadIdx.x & 255;       // thread within head
    int wid = tid >> 5, lane = tid & 31;

    float d = 1.0f / (1.0f + expf(-decay[n]));
    float od = 1.0f - d;

    const float* __restrict__ hp = g_h + (size_t)b * TT * NHH + n;
    int t0 = tid * CH;

    // Pass 1: local chunk EMA from 0 (16 independent loads, L2-resident)
    float ema = 0.0f;
#pragma unroll
    for (int i = 0; i < CH; i++)
        ema = d * ema + od * __ldg(&hp[(t0 + i) * NHH]);

    // A = d^16
    float A = d;
#pragma unroll
    for (int s = 0; s < 4; s++) A = A * A;

    // Warp inclusive Kogge-Stone scan of affine maps (a,bq): e -> a*e + bq
    float a = A, bq = ema;
#pragma unroll
    for (int off = 1; off < 32; off <<= 1) {
        float ap = __shfl_up_sync(0xffffffffu, a, off);
        float bp = __shfl_up_sync(0xffffffffu, bq, off);
        if (lane >= off) { bq = a * bp + bq; a = a * ap; }
    }

    __shared__ float sa[NHH][8], sb[NHH][8], smax[NHH][8], spart[NHH];
    if (lane == 31) { sa[n][wid] = a; sb[n][wid] = bq; }
    __syncthreads();

    // Exclusive prefix across the 8 warps of this head
    float e_w = 0.0f;
#pragma unroll
    for (int w = 0; w < 8; w++)
        if (w < wid) e_w = sa[n][w] * e_w + sb[n][w];

    float a_ex = __shfl_up_sync(0xffffffffu, a, 1);
    float b_ex = __shfl_up_sync(0xffffffffu, bq, 1);
    float e_in = (lane == 0) ? e_w : (a_ex * e_w + b_ex);

    // Pass 2: replay with incoming state, track max (init 0 per reference)
    ema = e_in;
    float emax = 0.0f;
#pragma unroll
    for (int i = 0; i < CH; i++) {
        ema = d * ema + od * __ldg(&hp[(t0 + i) * NHH]);
        emax = fmaxf(emax, ema);
    }

#pragma unroll
    for (int off = 16; off > 0; off >>= 1)
        emax = fmaxf(emax, __shfl_xor_sync(0xffffffffu, emax, off));
    if (lane == 0) smax[n][wid] = emax;
    __syncthreads();

    if (tid == 0) {  // one thread per head
        float m = smax[n][0];
#pragma unroll
        for (int w = 1; w < 8; w++) m = fmaxf(m, smax[n][w]);
        spart[n] = m * head_w[n];
    }
    __syncthreads();
    if (threadIdx.x == 0)
        out[b] = spart[0] + spart[1] + spart[2] + spart[3];
}

// ---------------------------------------------------------------------------
extern "C" void kernel_launch(void* const* d_in, const int* in_sizes, int n_in,
                              void* d_out, int out_size) {
    const float* x      = (const float*)d_in[0];
    const float* W      = (const float*)d_in[1];
    const float* bias   = (const float*)d_in[2];
    const float* decay  = (const float*)d_in[3];
    const float* head_w = (const float*)d_in[4];
    float* out = (float*)d_out;

    // B*T = 262144 rows, 4 rows/warp, 8 warps/block -> 8192 blocks
    int blocks = (BB * TT) / (4 * 8);
    k_gemv<<<blocks, 256>>>(x, W, bias);
    k_scan<<<BB, 1024>>>(decay, head_w, out);
}

// round 10
// speedup vs baseline: 1.0703x; 1.0703x over previous
#include <cuda_runtime.h>

#define BB  64
#define TT  4096
#define HH  1024
#define NHH 4

// Scratch, TRANSPOSED: h[b][n][t] : [B, NH, T] = 4 MB (L2-resident for scan)
__device__ float g_h[BB * NHH * TT];
__device__ float g_part[BB * NHH];

// ---------------------------------------------------------------------------
// Kernel 1: persistent tall-skinny GEMV. Each block loads W into smem ONCE,
// then loops over 32-row tiles (8 warps x 4 rows). x read with streaming hint.
// Stores h transposed per head plane for a coalesced scan.
// ---------------------------------------------------------------------------
__global__ __launch_bounds__(256) void k_gemv(const float* __restrict__ x,
                                              const float* __restrict__ W,
                                              const float* __restrict__ bias) {
    __shared__ float4 sW[NHH * (HH / 4)];  // 16 KB
    for (int i = threadIdx.x; i < NHH * (HH / 4); i += 256)
        sW[i] = reinterpret_cast<const float4*>(W)[i];
    __syncthreads();

    const int ROWS = 4;
    const int TILES = (BB * TT) / 32;  // 32 rows per block-tile
    int warp = threadIdx.x >> 5;
    int lane = threadIdx.x & 31;
    float b0 = bias[0], b1 = bias[1], b2 = bias[2], b3 = bias[3];

    for (int tile = blockIdx.x; tile < TILES; tile += gridDim.x) {
        long row0 = (long)tile * 32 + warp * ROWS;

        float acc[ROWS][NHH];
#pragma unroll
        for (int r = 0; r < ROWS; r++)
#pragma unroll
            for (int n = 0; n < NHH; n++) acc[r][n] = 0.0f;

        const float4* xp = reinterpret_cast<const float4*>(x) + row0 * (HH / 4);

#pragma unroll
        for (int k = 0; k < (HH / 4) / 32; k++) {  // 8 iterations
            int idx = lane + k * 32;
            float4 w0 = sW[0 * (HH / 4) + idx];
            float4 w1 = sW[1 * (HH / 4) + idx];
            float4 w2 = sW[2 * (HH / 4) + idx];
            float4 w3 = sW[3 * (HH / 4) + idx];
#pragma unroll
            for (int r = 0; r < ROWS; r++) {
                float4 xv = __ldcs(&xp[(long)r * (HH / 4) + idx]);
                acc[r][0] += xv.x * w0.x + xv.y * w0.y + xv.z * w0.z + xv.w * w0.w;
                acc[r][1] += xv.x * w1.x + xv.y * w1.y + xv.z * w1.z + xv.w * w1.w;
                acc[r][2] += xv.x * w2.x + xv.y * w2.y + xv.z * w2.z + xv.w * w2.w;
                acc[r][3] += xv.x * w3.x + xv.y * w3.y + xv.z * w3.z + xv.w * w3.w;
            }
        }

#pragma unroll
        for (int r = 0; r < ROWS; r++)
#pragma unroll
            for (int n = 0; n < NHH; n++)
#pragma unroll
                for (int off = 16; off > 0; off >>= 1)
                    acc[r][n] += __shfl_xor_sync(0xffffffffu, acc[r][n], off);

        if (lane == 0) {
            int b = (int)(row0 / TT);
            int t = (int)(row0 % TT);
            // Transposed store: plane (b, n), 4 consecutive t per float4
            float4* o0 = reinterpret_cast<float4*>(g_h + ((size_t)b * NHH + 0) * TT + t);
            float4* o1 = reinterpret_cast<float4*>(g_h + ((size_t)b * NHH + 1) * TT + t);
            float4* o2 = reinterpret_cast<float4*>(g_h + ((size_t)b * NHH + 2) * TT + t);
            float4* o3 = reinterpret_cast<float4*>(g_h + ((size_t)b * NHH + 3) * TT + t);
            *o0 = make_float4(acc[0][0] + b0, acc[1][0] + b0, acc[2][0] + b0, acc[3][0] + b0);
            *o1 = make_float4(acc[0][1] + b1, acc[1][1] + b1, acc[2][1] + b1, acc[3][1] + b1);
            *o2 = make_float4(acc[0][2] + b2, acc[1][2] + b2, acc[2][2] + b2, acc[3][2] + b2);
            *o3 = make_float4(acc[0][3] + b3, acc[1][3] + b3, acc[2][3] + b3, acc[3][3] + b3);
        }
    }
}

// ---------------------------------------------------------------------------
// Kernel 2: chunked EMA scan + running max on the transposed layout.
// Grid (B, NH) = 256 blocks x 256 threads; thread owns 16 contiguous steps
// (4 float4 loads, kept in registers for the replay pass).
// ---------------------------------------------------------------------------
__global__ __launch_bounds__(256) void k_scan(const float* __restrict__ decay) {
    int b = blockIdx.x, n = blockIdx.y;
    int tid = threadIdx.x;
    int wid = tid >> 5, lane = tid & 31;

    float d = 1.0f / (1.0f + expf(-decay[n]));
    float od = 1.0f - d;

    const float4* hp4 = reinterpret_cast<const float4*>(
                            g_h + ((size_t)b * NHH + n) * TT) + tid * 4;

    // Load the 16-step chunk once (coalesced), keep in registers
    float4 v[4];
#pragma unroll
    for (int i = 0; i < 4; i++) v[i] = hp4[i];

    // Pass 1: local chunk EMA starting from 0
    float ema = 0.0f;
#pragma unroll
    for (int i = 0; i < 4; i++) {
        ema = d * ema + od * v[i].x;
        ema = d * ema + od * v[i].y;
        ema = d * ema + od * v[i].z;
        ema = d * ema + od * v[i].w;
    }

    // A = d^16
    float A = d;
#pragma unroll
    for (int s = 0; s < 4; s++) A = A * A;

    // Warp inclusive Kogge-Stone scan of affine maps (a,bq): e -> a*e + bq
    float a = A, bq = ema;
#pragma unroll
    for (int off = 1; off < 32; off <<= 1) {
        float ap = __shfl_up_sync(0xffffffffu, a, off);
        float bp = __shfl_up_sync(0xffffffffu, bq, off);
        if (lane >= off) { bq = a * bp + bq; a = a * ap; }
    }

    __shared__ float sa[8], sb[8], smax[8];
    if (lane == 31) { sa[wid] = a; sb[wid] = bq; }
    __syncthreads();

    float e_w = 0.0f;
#pragma unroll
    for (int w = 0; w < 8; w++)
        if (w < wid) e_w = sa[w] * e_w + sb[w];

    float a_ex = __shfl_up_sync(0xffffffffu, a, 1);
    float b_ex = __shfl_up_sync(0xffffffffu, bq, 1);
    float e_in = (lane == 0) ? e_w : (a_ex * e_w + b_ex);

    // Pass 2: replay from registers with incoming state, track max (init 0)
    ema = e_in;
    float emax = 0.0f;
#pragma unroll
    for (int i = 0; i < 4; i++) {
        ema = d * ema + od * v[i].x; emax = fmaxf(emax, ema);
        ema = d * ema + od * v[i].y; emax = fmaxf(emax, ema);
        ema = d * ema + od * v[i].z; emax = fmaxf(emax, ema);
        ema = d * ema + od * v[i].w; emax = fmaxf(emax, ema);
    }

#pragma unroll
    for (int off = 16; off > 0; off >>= 1)
        emax = fmaxf(emax, __shfl_xor_sync(0xffffffffu, emax, off));
    if (lane == 0) smax[wid] = emax;
    __syncthreads();
    if (tid == 0) {
        float m = smax[0];
#pragma unroll
        for (int w = 1; w < 8; w++) m = fmaxf(m, smax[w]);
        g_part[b * NHH + n] = m;
    }
}

// ---------------------------------------------------------------------------
// Kernel 3: head projection
// ---------------------------------------------------------------------------
__global__ void k_final(const float* __restrict__ head_w,
                        float* __restrict__ out) {
    int b = threadIdx.x;
    if (b < BB) {
        float s = 0.0f;
#pragma unroll
        for (int n = 0; n < NHH; n++)
            s += g_part[b * NHH + n] * head_w[n];
        out[b] = s;
    }
}

// ---------------------------------------------------------------------------
extern "C" void kernel_launch(void* const* d_in, const int* in_sizes, int n_in,
                              void* d_out, int out_size) {
    const float* x      = (const float*)d_in[0];
    const float* W      = (const float*)d_in[1];
    const float* bias   = (const float*)d_in[2];
    const float* decay  = (const float*)d_in[3];
    const float* head_w = (const float*)d_in[4];
    float* out = (float*)d_out;

    // Persistent grid: ~3 blocks/SM on 152 SMs
    k_gemv<<<456, 256>>>(x, W, bias);
    dim3 sg(BB, NHH);
    k_scan<<<sg, 256>>>(decay);
    k_final<<<1, 64>>>(head_w, out);
}

// round 11
// speedup vs baseline: 1.1604x; 1.0842x over previous
#include <cuda_runtime.h>

#define BB  64
#define TT  4096
#define HH  1024
#define NHH 4

// Scratch, TRANSPOSED: h[b][n][t] : [B, NH, T] = 4 MB (L2-resident for scan)
__device__ float g_h[BB * NHH * TT];
__device__ float g_part[BB * NHH];
__device__ int   g_cnt;  // scan-block completion counter (reset in-kernel)

// ---------------------------------------------------------------------------
// Kernel 1: tall-skinny GEMV — exact R3 structure (one-shot 8192 blocks,
// 8 warps x 4 rows, W staged in smem, natural register allocation).
// Only change: stores go to the transposed [b][n][t] layout.
// ---------------------------------------------------------------------------
__global__ __launch_bounds__(256) void k_gemv(const float* __restrict__ x,
                                              const float* __restrict__ W,
                                              const float* __restrict__ bias) {
    __shared__ float4 sW[NHH * (HH / 4)];  // 16 KB
    for (int i = threadIdx.x; i < NHH * (HH / 4); i += 256)
        sW[i] = reinterpret_cast<const float4*>(W)[i];
    __syncthreads();

    const int ROWS = 4;
    int warp_global = (blockIdx.x * 256 + threadIdx.x) >> 5;
    int lane = threadIdx.x & 31;
    long row0 = (long)warp_global * ROWS;

    float acc[ROWS][NHH];
#pragma unroll
    for (int r = 0; r < ROWS; r++)
#pragma unroll
        for (int n = 0; n < NHH; n++) acc[r][n] = 0.0f;

    const float4* xp = reinterpret_cast<const float4*>(x) + row0 * (HH / 4);

#pragma unroll
    for (int k = 0; k < (HH / 4) / 32; k++) {  // 8 iterations
        int idx = lane + k * 32;
        float4 w0 = sW[0 * (HH / 4) + idx];
        float4 w1 = sW[1 * (HH / 4) + idx];
        float4 w2 = sW[2 * (HH / 4) + idx];
        float4 w3 = sW[3 * (HH / 4) + idx];
#pragma unroll
        for (int r = 0; r < ROWS; r++) {
            float4 xv = xp[(long)r * (HH / 4) + idx];
            acc[r][0] += xv.x * w0.x + xv.y * w0.y + xv.z * w0.z + xv.w * w0.w;
            acc[r][1] += xv.x * w1.x + xv.y * w1.y + xv.z * w1.z + xv.w * w1.w;
            acc[r][2] += xv.x * w2.x + xv.y * w2.y + xv.z * w2.z + xv.w * w2.w;
            acc[r][3] += xv.x * w3.x + xv.y * w3.y + xv.z * w3.z + xv.w * w3.w;
        }
    }

#pragma unroll
    for (int r = 0; r < ROWS; r++)
#pragma unroll
        for (int n = 0; n < NHH; n++)
#pragma unroll
            for (int off = 16; off > 0; off >>= 1)
                acc[r][n] += __shfl_xor_sync(0xffffffffu, acc[r][n], off);

    if (lane == 0) {
        float b0 = bias[0], b1 = bias[1], b2 = bias[2], b3 = bias[3];
        int b = (int)(row0 / TT);
        int t = (int)(row0 % TT);  // 4 consecutive t, same batch
        float* plane = g_h + (size_t)b * NHH * TT + t;
        *reinterpret_cast<float4*>(plane + 0 * TT) =
            make_float4(acc[0][0] + b0, acc[1][0] + b0, acc[2][0] + b0, acc[3][0] + b0);
        *reinterpret_cast<float4*>(plane + 1 * TT) =
            make_float4(acc[0][1] + b1, acc[1][1] + b1, acc[2][1] + b1, acc[3][1] + b1);
        *reinterpret_cast<float4*>(plane + 2 * TT) =
            make_float4(acc[0][2] + b2, acc[1][2] + b2, acc[2][2] + b2, acc[3][2] + b2);
        *reinterpret_cast<float4*>(plane + 3 * TT) =
            make_float4(acc[0][3] + b3, acc[1][3] + b3, acc[2][3] + b3, acc[3][3] + b3);
    }
}

// ---------------------------------------------------------------------------
// Kernel 2: chunked EMA scan + running max on contiguous planes, with the
// LAST block doing the head projection (no third kernel). Grid (B, NH) x 256.
// ---------------------------------------------------------------------------
__global__ __launch_bounds__(256) void k_scan(const float* __restrict__ decay,
                                              const float* __restrict__ head_w,
                                              float* __restrict__ out) {
    int b = blockIdx.x, n = blockIdx.y;
    int tid = threadIdx.x;
    int wid = tid >> 5, lane = tid & 31;

    float d = 1.0f / (1.0f + expf(-decay[n]));
    float od = 1.0f - d;

    const float4* hp4 = reinterpret_cast<const float4*>(
                            g_h + ((size_t)b * NHH + n) * TT) + tid * 4;

    // 16-step chunk, loaded once (L1/L2-friendly contiguous), kept in regs
    float4 v[4];
#pragma unroll
    for (int i = 0; i < 4; i++) v[i] = hp4[i];

    // Pass 1: local chunk EMA from 0
    float ema = 0.0f;
#pragma unroll
    for (int i = 0; i < 4; i++) {
        ema = d * ema + od * v[i].x;
        ema = d * ema + od * v[i].y;
        ema = d * ema + od * v[i].z;
        ema = d * ema + od * v[i].w;
    }

    // A = d^16
    float A = d;
#pragma unroll
    for (int s = 0; s < 4; s++) A = A * A;

    // Warp inclusive Kogge-Stone scan of affine maps (a,bq): e -> a*e + bq
    float a = A, bq = ema;
#pragma unroll
    for (int off = 1; off < 32; off <<= 1) {
        float ap = __shfl_up_sync(0xffffffffu, a, off);
        float bp = __shfl_up_sync(0xffffffffu, bq, off);
        if (lane >= off) { bq = a * bp + bq; a = a * ap; }
    }

    __shared__ float sa[8], sb[8], smax[8];
    __shared__ int s_last;
    if (lane == 31) { sa[wid] = a; sb[wid] = bq; }
    __syncthreads();

    float e_w = 0.0f;
#pragma unroll
    for (int w = 0; w < 8; w++)
        if (w < wid) e_w = sa[w] * e_w + sb[w];

    float a_ex = __shfl_up_sync(0xffffffffu, a, 1);
    float b_ex = __shfl_up_sync(0xffffffffu, bq, 1);
    float e_in = (lane == 0) ? e_w : (a_ex * e_w + b_ex);

    // Pass 2: replay from registers, track max (init 0 per reference)
    ema = e_in;
    float emax = 0.0f;
#pragma unroll
    for (int i = 0; i < 4; i++) {
        ema = d * ema + od * v[i].x; emax = fmaxf(emax, ema);
        ema = d * ema + od * v[i].y; emax = fmaxf(emax, ema);
        ema = d * ema + od * v[i].z; emax = fmaxf(emax, ema);
        ema = d * ema + od * v[i].w; emax = fmaxf(emax, ema);
    }

#pragma unroll
    for (int off = 16; off > 0; off >>= 1)
        emax = fmaxf(emax, __shfl_xor_sync(0xffffffffu, emax, off));
    if (lane == 0) smax[wid] = emax;
    __syncthreads();

    if (tid == 0) {
        float m = smax[0];
#pragma unroll
        for (int w = 1; w < 8; w++) m = fmaxf(m, smax[w]);
        g_part[b * NHH + n] = m;
        __threadfence();  // release g_part before counter bump
        int prev = atomicAdd(&g_cnt, 1);
        s_last = (prev == BB * NHH - 1);
    }
    __syncthreads();

    // Last block: all partials visible -> head projection + counter reset
    if (s_last) {
        __threadfence();  // acquire
        if (tid < BB) {
            const volatile float* gp = g_part;
            float s = 0.0f;
#pragma unroll
            for (int nn = 0; nn < NHH; nn++)
                s += gp[tid * NHH + nn] * head_w[nn];
            out[tid] = s;
        }
        __syncthreads();
        if (tid == 0) g_cnt = 0;  // clean for next graph replay
    }
}

// ---------------------------------------------------------------------------
extern "C" void kernel_launch(void* const* d_in, const int* in_sizes, int n_in,
                              void* d_out, int out_size) {
    const float* x      = (const float*)d_in[0];
    const float* W      = (const float*)d_in[1];
    const float* bias   = (const float*)d_in[2];
    const float* decay  = (const float*)d_in[3];
    const float* head_w = (const float*)d_in[4];
    float* out = (float*)d_out;

    // B*T = 262144 rows, 4 rows/warp, 8 warps/block -> 8192 blocks
    int blocks = (BB * TT) / (4 * 8);
    k_gemv<<<blocks, 256>>>(x, W, bias);
    dim3 sg(BB, NHH);
    k_scan<<<sg, 256>>>(decay, head_w, out);
}